// round 10
// baseline (speedup 1.0000x reference)
#include <cuda_runtime.h>
#include <cstdint>

// Problem constants
#define HID   512
#define NSTEP 8192          // BS*T = 1024*8
#define G4H   2048          // 4*HID
#define DIN   512

// Scan kernel config: CTAs 0..63 = forward, 64..127 = backward.
#define NC           128
#define SCAN_THREADS 512
#define HC           8      // hidden indices per CTA (single direction)

// GEMM config
#define BM 128
#define BN 128
#define BK 16

__device__ float g_gates[(size_t)2 * NSTEP * G4H];
__device__ __align__(128) unsigned long long g_hbuf[2][2][HID];  // [dir][parity][e]

// ---------------------------------------------------------------------------
__device__ __forceinline__ void st_rel(unsigned long long* p, unsigned long long v) {
    asm volatile("st.global.relaxed.gpu.u64 [%0], %1;" :: "l"(p), "l"(v) : "memory");
}
__device__ __forceinline__ unsigned long long ld_rel(const unsigned long long* p) {
    unsigned long long v;
    asm volatile("ld.relaxed.gpu.global.u64 %0, [%1];" : "=l"(v) : "l"(p) : "memory");
    return v;
}
// Hardware tanh (MUFU.TANH): one op per transcendental.
__device__ __forceinline__ float htanh(float x) {
    float y;
    asm("tanh.approx.f32 %0, %1;" : "=f"(y) : "f"(x));
    return y;
}
__device__ __forceinline__ float hsigmoid(float x) {
    return fmaf(htanh(0.5f * x), 0.5f, 0.5f);
}

// ---------------------------------------------------------------------------
// Kernel 1: gates GEMM (unchanged — measured good).
// ---------------------------------------------------------------------------
__global__ __launch_bounds__(256) void gates_gemm(
    const float* __restrict__ x,
    const float* __restrict__ Wif, const float* __restrict__ bf,
    const float* __restrict__ Wib, const float* __restrict__ bb)
{
    const int dir = blockIdx.z;
    const float* __restrict__ W    = dir ? Wib : Wif;
    const float* __restrict__ bias = dir ? bb  : bf;
    float* __restrict__ out = g_gates + (size_t)dir * NSTEP * G4H;

    __shared__ __align__(16) float As[BK][BM + 4];
    __shared__ __align__(16) float Bs[BK][BN + 4];

    const int tid  = threadIdx.x;
    const int row0 = blockIdx.y * BM;
    const int col0 = blockIdx.x * BN;
    const int tx = tid & 15;
    const int ty = tid >> 4;

    float acc[8][8];
    #pragma unroll
    for (int i = 0; i < 8; i++)
        #pragma unroll
        for (int j = 0; j < 8; j++) acc[i][j] = 0.f;

    for (int k0 = 0; k0 < DIN; k0 += BK) {
        #pragma unroll
        for (int l = 0; l < 2; l++) {
            int idx = tid + l * 256;
            int m   = idx >> 2;
            int kq  = (idx & 3) * 4;
            int srow = row0 + m;
            int xrow = dir ? (srow ^ 7) : srow;
            float4 v = *(const float4*)&x[(size_t)xrow * DIN + k0 + kq];
            As[kq + 0][m] = v.x; As[kq + 1][m] = v.y;
            As[kq + 2][m] = v.z; As[kq + 3][m] = v.w;
            float4 w = *(const float4*)&W[(size_t)(col0 + m) * DIN + k0 + kq];
            Bs[kq + 0][m] = w.x; Bs[kq + 1][m] = w.y;
            Bs[kq + 2][m] = w.z; Bs[kq + 3][m] = w.w;
        }
        __syncthreads();
        #pragma unroll
        for (int kk = 0; kk < BK; kk++) {
            float a[8], b[8];
            float4 a0 = *(const float4*)&As[kk][ty * 8];
            float4 a1 = *(const float4*)&As[kk][ty * 8 + 4];
            a[0]=a0.x; a[1]=a0.y; a[2]=a0.z; a[3]=a0.w;
            a[4]=a1.x; a[5]=a1.y; a[6]=a1.z; a[7]=a1.w;
            float4 b0 = *(const float4*)&Bs[kk][tx * 8];
            float4 b1 = *(const float4*)&Bs[kk][tx * 8 + 4];
            b[0]=b0.x; b[1]=b0.y; b[2]=b0.z; b[3]=b0.w;
            b[4]=b1.x; b[5]=b1.y; b[6]=b1.z; b[7]=b1.w;
            #pragma unroll
            for (int i = 0; i < 8; i++)
                #pragma unroll
                for (int j = 0; j < 8; j++)
                    acc[i][j] = fmaf(a[i], b[j], acc[i][j]);
        }
        __syncthreads();
    }

    #pragma unroll
    for (int i = 0; i < 8; i++) {
        size_t srow = row0 + ty * 8 + i;
        #pragma unroll
        for (int j = 0; j < 8; j++) {
            int c = col0 + tx * 8 + j;
            out[srow * G4H + c] = acc[i][j] + bias[c];
        }
    }
}

// ---------------------------------------------------------------------------
// Kernel 2: direction-split persistent scan, 4-deep pipelined spin poll.
// ---------------------------------------------------------------------------
__global__ void __launch_bounds__(SCAN_THREADS, 1) lstm_scan(
    const float* __restrict__ h0,
    const float* __restrict__ c0,
    const float* __restrict__ Whf,
    const float* __restrict__ Whb,
    float* __restrict__ out)
{
    const int cta   = blockIdx.x;
    const int tid   = threadIdx.x;
    const int dir   = cta >> 6;          // 0 fwd / 1 bwd
    const int ebase = (cta & 63) * HC;   // first owned hidden index

    __shared__ __align__(16) float sh[2][HID];      // own-dir hidden state
    __shared__ __align__(16) float part[32][64];    // [gate*8 + h'][slice]
    __shared__ float zbuf[32];

    // ---- matvec role: gate, h'-half, h-slice ----
    const int og = (tid >> 6) & 3;       // gate 0..3
    const int hh = tid >> 8;             // 0: h' 0..3, 1: h' 4..7
    const int hs = tid & 63;             // h slice [hs*8, hs*8+8)

    const float* __restrict__ Wd = dir ? Whb : Whf;
    float w[4][8];                       // 4 outputs (q) x 8 h-elems
    #pragma unroll
    for (int q = 0; q < 4; q++) {
        size_t row = (size_t)og * HID + ebase + hh * 4 + q;
        #pragma unroll
        for (int k = 0; k < 8; k++)
            w[q][k] = Wd[row * HID + hs * 8 + k];
    }

    // ---- reduce role ----
    const int row = tid >> 4;            // 0..31 = gate*8 + h'
    const int sub = tid & 15;
    const int rg  = row >> 3;            // gate
    const int rh  = row & 7;             // h'
    const size_t gq_base = (size_t)dir * NSTEP * G4H
                         + (size_t)rg * HID + ebase + rh;
    float gcur = 0.f;
    if (sub == 0) gcur = __ldg(g_gates + gq_base);

    // ---- update role (tid<8): owns h' = tid ----
    float cst = 0.f, hv = 0.f;
    if (tid < 8) {
        int e = ebase + tid;
        hv  = h0[dir * HID + e];
        cst = c0[dir * HID + e];
        unsigned long long pk =
            (((unsigned long long)1u) << 32) | (unsigned long long)__float_as_uint(hv);
        st_rel(&g_hbuf[dir][0][e], pk);
    }

    for (int s = 0; s < NSTEP; s++) {
        // Phase 1: 4-deep software-pipelined spin poll (1 slot per thread).
        // Keeps 4 relaxed loads in flight; checks the oldest each iteration,
        // cutting detection granularity from ~L2 latency to ~latency/4.
        {
            const unsigned want = (unsigned)(s + 1);
            const unsigned long long* bp = &g_hbuf[dir][s & 1][tid];
            unsigned long long v0 = ld_rel(bp);
            unsigned long long v1 = ld_rel(bp);
            unsigned long long v2 = ld_rel(bp);
            unsigned long long v3 = ld_rel(bp);
            while ((unsigned)(v0 >> 32) != want) {
                v0 = v1; v1 = v2; v2 = v3;
                v3 = ld_rel(bp);
            }
            sh[s & 1][tid] = __uint_as_float((unsigned)v0);
        }
        __syncthreads();   // S1

        // Phase 2: register-tiled matvec partials (plain FFMA)
        {
            float4 ha = *(const float4*)&sh[s & 1][hs * 8];
            float4 hb = *(const float4*)&sh[s & 1][hs * 8 + 4];
            float hr[8] = {ha.x, ha.y, ha.z, ha.w, hb.x, hb.y, hb.z, hb.w};
            float a0 = 0.f, a1 = 0.f, a2 = 0.f, a3 = 0.f;
            #pragma unroll
            for (int k = 0; k < 8; k++) {
                float h = hr[k];
                a0 = fmaf(w[0][k], h, a0);
                a1 = fmaf(w[1][k], h, a1);
                a2 = fmaf(w[2][k], h, a2);
                a3 = fmaf(w[3][k], h, a3);
            }
            int prow = og * 8 + hh * 4;
            part[prow + 0][hs] = a0;
            part[prow + 1][hs] = a1;
            part[prow + 2][hs] = a2;
            part[prow + 3][hs] = a3;
        }
        __syncthreads();   // S2

        // Phase 3: reduce 64 partials per output
        {
            float4 p = *(const float4*)&part[row][sub << 2];
            float sv = (p.x + p.y) + (p.z + p.w);
            sv += __shfl_xor_sync(0xffffffffu, sv, 1);
            sv += __shfl_xor_sync(0xffffffffu, sv, 2);
            sv += __shfl_xor_sync(0xffffffffu, sv, 4);
            sv += __shfl_xor_sync(0xffffffffu, sv, 8);
            if (sub == 0) zbuf[row] = sv + gcur;
        }
        __syncthreads();   // S3

        // Phase 4: gates (MUFU.TANH) + state update + PUBLISH
        if (tid < 8) {
            float zi = zbuf[0  + tid];
            float zf = zbuf[8  + tid];
            float zg = zbuf[16 + tid];
            float zo = zbuf[24 + tid];
            float ig = hsigmoid(zi);
            float fg = hsigmoid(zf);
            float gg = htanh(zg);
            float oo = hsigmoid(zo);
            cst = fmaf(fg, cst, ig * gg);
            hv  = oo * htanh(cst);

            int e = ebase + tid;
            unsigned long long pk =
                (((unsigned long long)(unsigned)(s + 2)) << 32) |
                (unsigned long long)__float_as_uint(hv);
            st_rel(&g_hbuf[dir][(s + 1) & 1][e], pk);
        }
        __syncthreads();   // S4 — hold poll flood until all publishes issued

        // Phase 5 (off critical path): output store + next gate prefetch
        if (tid < 8) {
            int e = ebase + tid;
            size_t orow = dir ? (size_t)(s ^ 7) : (size_t)s;
            out[orow * (2 * HID) + dir * HID + e] = hv;
            if (s == NSTEP - 1) {
                out[(size_t)NSTEP * 2 * HID + dir * HID + e] = hv;
                out[(size_t)NSTEP * 2 * HID + 2 * HID + dir * HID + e] = cst;
            }
        }
        if (sub == 0) {
            int ns = (s + 1 < NSTEP) ? (s + 1) : (NSTEP - 1);
            gcur = __ldg(g_gates + gq_base + (size_t)ns * G4H);
        }
    }
}

// ---------------------------------------------------------------------------
extern "C" void kernel_launch(void* const* d_in, const int* in_sizes, int n_in,
                              void* d_out, int out_size)
{
    const float* x   = (const float*)d_in[0];
    const float* h0  = (const float*)d_in[1];
    const float* c0  = (const float*)d_in[2];
    const float* Wif = (const float*)d_in[3];
    const float* Whf = (const float*)d_in[4];
    const float* bf  = (const float*)d_in[5];
    const float* Wib = (const float*)d_in[6];
    const float* Whb = (const float*)d_in[7];
    const float* bb  = (const float*)d_in[8];
    float* out = (float*)d_out;

    dim3 ggrid(G4H / BN, NSTEP / BM, 2);
    gates_gemm<<<ggrid, 256>>>(x, Wif, bf, Wib, bb);
    lstm_scan<<<NC, SCAN_THREADS>>>(h0, c0, Whf, Whb, out);
}

// round 11
// speedup vs baseline: 1.2272x; 1.2272x over previous
#include <cuda_runtime.h>
#include <cstdint>

// Problem constants
#define HID   512
#define NSTEP 8192          // BS*T = 1024*8
#define G4H   2048          // 4*HID
#define DIN   512

// Scan kernel config: CTAs 0..63 = forward, 64..127 = backward.
#define NC           128
#define SCAN_THREADS 512
#define HC           8      // hidden indices per CTA (single direction)

// GEMM config
#define BM 128
#define BN 128
#define BK 16

__device__ float g_gates[(size_t)2 * NSTEP * G4H];
__device__ __align__(128) unsigned long long g_hbuf[2][2][HID];  // [dir][parity][e]

// ---------------------------------------------------------------------------
__device__ __forceinline__ void st_rel(unsigned long long* p, unsigned long long v) {
    asm volatile("st.global.relaxed.gpu.u64 [%0], %1;" :: "l"(p), "l"(v) : "memory");
}
__device__ __forceinline__ void ld_rel_v2(const unsigned long long* p,
                                          unsigned long long& a, unsigned long long& b) {
    asm volatile("ld.relaxed.gpu.global.v2.u64 {%0, %1}, [%2];"
                 : "=l"(a), "=l"(b) : "l"(p) : "memory");
}
// Hardware tanh (MUFU.TANH): one op per transcendental.
__device__ __forceinline__ float htanh(float x) {
    float y;
    asm("tanh.approx.f32 %0, %1;" : "=f"(y) : "f"(x));
    return y;
}
__device__ __forceinline__ float hsigmoid(float x) {
    return fmaf(htanh(0.5f * x), 0.5f, 0.5f);
}

// ---------------------------------------------------------------------------
// Kernel 1: gates GEMM (unchanged — measured good).
// ---------------------------------------------------------------------------
__global__ __launch_bounds__(256) void gates_gemm(
    const float* __restrict__ x,
    const float* __restrict__ Wif, const float* __restrict__ bf,
    const float* __restrict__ Wib, const float* __restrict__ bb)
{
    const int dir = blockIdx.z;
    const float* __restrict__ W    = dir ? Wib : Wif;
    const float* __restrict__ bias = dir ? bb  : bf;
    float* __restrict__ out = g_gates + (size_t)dir * NSTEP * G4H;

    __shared__ __align__(16) float As[BK][BM + 4];
    __shared__ __align__(16) float Bs[BK][BN + 4];

    const int tid  = threadIdx.x;
    const int row0 = blockIdx.y * BM;
    const int col0 = blockIdx.x * BN;
    const int tx = tid & 15;
    const int ty = tid >> 4;

    float acc[8][8];
    #pragma unroll
    for (int i = 0; i < 8; i++)
        #pragma unroll
        for (int j = 0; j < 8; j++) acc[i][j] = 0.f;

    for (int k0 = 0; k0 < DIN; k0 += BK) {
        #pragma unroll
        for (int l = 0; l < 2; l++) {
            int idx = tid + l * 256;
            int m   = idx >> 2;
            int kq  = (idx & 3) * 4;
            int srow = row0 + m;
            int xrow = dir ? (srow ^ 7) : srow;
            float4 v = *(const float4*)&x[(size_t)xrow * DIN + k0 + kq];
            As[kq + 0][m] = v.x; As[kq + 1][m] = v.y;
            As[kq + 2][m] = v.z; As[kq + 3][m] = v.w;
            float4 w = *(const float4*)&W[(size_t)(col0 + m) * DIN + k0 + kq];
            Bs[kq + 0][m] = w.x; Bs[kq + 1][m] = w.y;
            Bs[kq + 2][m] = w.z; Bs[kq + 3][m] = w.w;
        }
        __syncthreads();
        #pragma unroll
        for (int kk = 0; kk < BK; kk++) {
            float a[8], b[8];
            float4 a0 = *(const float4*)&As[kk][ty * 8];
            float4 a1 = *(const float4*)&As[kk][ty * 8 + 4];
            a[0]=a0.x; a[1]=a0.y; a[2]=a0.z; a[3]=a0.w;
            a[4]=a1.x; a[5]=a1.y; a[6]=a1.z; a[7]=a1.w;
            float4 b0 = *(const float4*)&Bs[kk][tx * 8];
            float4 b1 = *(const float4*)&Bs[kk][tx * 8 + 4];
            b[0]=b0.x; b[1]=b0.y; b[2]=b0.z; b[3]=b0.w;
            b[4]=b1.x; b[5]=b1.y; b[6]=b1.z; b[7]=b1.w;
            #pragma unroll
            for (int i = 0; i < 8; i++)
                #pragma unroll
                for (int j = 0; j < 8; j++)
                    acc[i][j] = fmaf(a[i], b[j], acc[i][j]);
        }
        __syncthreads();
    }

    #pragma unroll
    for (int i = 0; i < 8; i++) {
        size_t srow = row0 + ty * 8 + i;
        #pragma unroll
        for (int j = 0; j < 8; j++) {
            int c = col0 + tx * 8 + j;
            out[srow * G4H + c] = acc[i][j] + bias[c];
        }
    }
}

// ---------------------------------------------------------------------------
// Kernel 2: direction-split persistent scan (R9 base).
// Poll: threads 0..255 each poll 2 slots with one LDG.128 (halved requests).
// ---------------------------------------------------------------------------
__global__ void __launch_bounds__(SCAN_THREADS, 1) lstm_scan(
    const float* __restrict__ h0,
    const float* __restrict__ c0,
    const float* __restrict__ Whf,
    const float* __restrict__ Whb,
    float* __restrict__ out)
{
    const int cta   = blockIdx.x;
    const int tid   = threadIdx.x;
    const int dir   = cta >> 6;          // 0 fwd / 1 bwd
    const int ebase = (cta & 63) * HC;   // first owned hidden index

    __shared__ __align__(16) float sh[2][HID];      // own-dir hidden state
    __shared__ __align__(16) float part[32][64];    // [gate*8 + h'][slice]
    __shared__ float zbuf[32];

    // ---- matvec role: gate, h'-half, h-slice ----
    const int og = (tid >> 6) & 3;       // gate 0..3
    const int hh = tid >> 8;             // 0: h' 0..3, 1: h' 4..7
    const int hs = tid & 63;             // h slice [hs*8, hs*8+8)

    const float* __restrict__ Wd = dir ? Whb : Whf;
    float w[4][8];                       // 4 outputs (q) x 8 h-elems
    #pragma unroll
    for (int q = 0; q < 4; q++) {
        size_t row = (size_t)og * HID + ebase + hh * 4 + q;
        #pragma unroll
        for (int k = 0; k < 8; k++)
            w[q][k] = Wd[row * HID + hs * 8 + k];
    }

    // ---- reduce role ----
    const int row = tid >> 4;            // 0..31 = gate*8 + h'
    const int sub = tid & 15;
    const int rg  = row >> 3;            // gate
    const int rh  = row & 7;             // h'
    const size_t gq_base = (size_t)dir * NSTEP * G4H
                         + (size_t)rg * HID + ebase + rh;
    float gcur = 0.f;
    if (sub == 0) gcur = __ldg(g_gates + gq_base);

    // ---- update role (tid<8): owns h' = tid ----
    float cst = 0.f, hv = 0.f;
    if (tid < 8) {
        int e = ebase + tid;
        hv  = h0[dir * HID + e];
        cst = c0[dir * HID + e];
        unsigned long long pk =
            (((unsigned long long)1u) << 32) | (unsigned long long)__float_as_uint(hv);
        st_rel(&g_hbuf[dir][0][e], pk);
    }

    for (int s = 0; s < NSTEP; s++) {
        // Phase 1: threads 0..255 poll 2 slots each with one LDG.128
        if (tid < 256) {
            const unsigned want = (unsigned)(s + 1);
            const unsigned long long* bp = &g_hbuf[dir][s & 1][tid * 2];
            unsigned long long v0, v1;
            do {
                ld_rel_v2(bp, v0, v1);
            } while ((unsigned)(v0 >> 32) != want || (unsigned)(v1 >> 32) != want);
            float2 hvals = make_float2(__uint_as_float((unsigned)v0),
                                       __uint_as_float((unsigned)v1));
            *(float2*)&sh[s & 1][tid * 2] = hvals;
        }
        __syncthreads();   // S1

        // Phase 2: register-tiled matvec partials (plain FFMA)
        {
            float4 ha = *(const float4*)&sh[s & 1][hs * 8];
            float4 hb = *(const float4*)&sh[s & 1][hs * 8 + 4];
            float hr[8] = {ha.x, ha.y, ha.z, ha.w, hb.x, hb.y, hb.z, hb.w};
            float a0 = 0.f, a1 = 0.f, a2 = 0.f, a3 = 0.f;
            #pragma unroll
            for (int k = 0; k < 8; k++) {
                float h = hr[k];
                a0 = fmaf(w[0][k], h, a0);
                a1 = fmaf(w[1][k], h, a1);
                a2 = fmaf(w[2][k], h, a2);
                a3 = fmaf(w[3][k], h, a3);
            }
            int prow = og * 8 + hh * 4;
            part[prow + 0][hs] = a0;
            part[prow + 1][hs] = a1;
            part[prow + 2][hs] = a2;
            part[prow + 3][hs] = a3;
        }
        __syncthreads();   // S2

        // Phase 3: reduce 64 partials per output
        {
            float4 p = *(const float4*)&part[row][sub << 2];
            float sv = (p.x + p.y) + (p.z + p.w);
            sv += __shfl_xor_sync(0xffffffffu, sv, 1);
            sv += __shfl_xor_sync(0xffffffffu, sv, 2);
            sv += __shfl_xor_sync(0xffffffffu, sv, 4);
            sv += __shfl_xor_sync(0xffffffffu, sv, 8);
            if (sub == 0) zbuf[row] = sv + gcur;
        }
        __syncthreads();   // S3

        // Phase 4: gates (MUFU.TANH) + state update + PUBLISH
        if (tid < 8) {
            float zi = zbuf[0  + tid];
            float zf = zbuf[8  + tid];
            float zg = zbuf[16 + tid];
            float zo = zbuf[24 + tid];
            float ig = hsigmoid(zi);
            float fg = hsigmoid(zf);
            float gg = htanh(zg);
            float oo = hsigmoid(zo);
            cst = fmaf(fg, cst, ig * gg);
            hv  = oo * htanh(cst);

            int e = ebase + tid;
            unsigned long long pk =
                (((unsigned long long)(unsigned)(s + 2)) << 32) |
                (unsigned long long)__float_as_uint(hv);
            st_rel(&g_hbuf[dir][(s + 1) & 1][e], pk);
        }
        __syncthreads();   // S4 — hold poll flood until all publishes issued

        // Phase 5 (off critical path): output store + next gate prefetch
        if (tid < 8) {
            int e = ebase + tid;
            size_t orow = dir ? (size_t)(s ^ 7) : (size_t)s;
            out[orow * (2 * HID) + dir * HID + e] = hv;
            if (s == NSTEP - 1) {
                out[(size_t)NSTEP * 2 * HID + dir * HID + e] = hv;
                out[(size_t)NSTEP * 2 * HID + 2 * HID + dir * HID + e] = cst;
            }
        }
        if (sub == 0) {
            int ns = (s + 1 < NSTEP) ? (s + 1) : (NSTEP - 1);
            gcur = __ldg(g_gates + gq_base + (size_t)ns * G4H);
        }
    }
}

// ---------------------------------------------------------------------------
extern "C" void kernel_launch(void* const* d_in, const int* in_sizes, int n_in,
                              void* d_out, int out_size)
{
    const float* x   = (const float*)d_in[0];
    const float* h0  = (const float*)d_in[1];
    const float* c0  = (const float*)d_in[2];
    const float* Wif = (const float*)d_in[3];
    const float* Whf = (const float*)d_in[4];
    const float* bf  = (const float*)d_in[5];
    const float* Wib = (const float*)d_in[6];
    const float* Whb = (const float*)d_in[7];
    const float* bb  = (const float*)d_in[8];
    float* out = (float*)d_out;

    dim3 ggrid(G4H / BN, NSTEP / BM, 2);
    gates_gemm<<<ggrid, 256>>>(x, Wif, bf, Wib, bb);
    lstm_scan<<<NC, SCAN_THREADS>>>(h0, c0, Whf, Whb, out);
}